// round 8
// baseline (speedup 1.0000x reference)
#include <cuda_runtime.h>
#include <cstdint>

// QuietAttention, single-pass unnormalized softmax, TQ=64/TK=64,
// 256 threads, 2 CTAs/SM, fragment-reuse 3-split MMA, wide converts.
// out [16,2048,128] fp32 then p_attn [16,2048,2049] fp32 in d_out.

#define BB 16
#define SS 2048
#define DD 128
#define SP1 2049
#define NTH 256
#define TQ 64
#define TK 64
#define PITCHB 272
#define PITCHP 144

#define OFF_QHI 0
#define OFF_QLO 17408
#define OFF_KHI 34816           // after QK: P hi
#define OFF_KLO 52224           // after QK: P lo
#define OFF_VHI 69632
#define OFF_VLO 87040
#define OFF_MB  104448
#define OFF_RM  104960
#define OFF_RZ  105984
#define OFF_SI  107008
#define SMEM_TOTAL 107264

__device__ __forceinline__ uint32_t smem_u32(const void* p) {
    uint32_t a;
    asm("{ .reg .u64 t; cvta.to.shared.u64 t, %1; cvt.u32.u64 %0, t; }" : "=r"(a) : "l"(p));
    return a;
}
__device__ __forceinline__ void pf_l2(const void* p) {
    asm volatile("prefetch.global.L2 [%0];" :: "l"(p));
}
__device__ __forceinline__ void ldsm4(uint32_t* r, uint32_t addr) {
    asm volatile("ldmatrix.sync.aligned.m8n8.x4.shared.b16 {%0,%1,%2,%3}, [%4];"
                 : "=r"(r[0]), "=r"(r[1]), "=r"(r[2]), "=r"(r[3]) : "r"(addr));
}
__device__ __forceinline__ void ldsm4t(uint32_t* r, uint32_t addr) {
    asm volatile("ldmatrix.sync.aligned.m8n8.x4.trans.shared.b16 {%0,%1,%2,%3}, [%4];"
                 : "=r"(r[0]), "=r"(r[1]), "=r"(r[2]), "=r"(r[3]) : "r"(addr));
}
__device__ __forceinline__ void mma16816(float* c, const uint32_t* a, const uint32_t* b) {
    asm volatile("mma.sync.aligned.m16n8k16.row.col.f32.bf16.bf16.f32 "
                 "{%0,%1,%2,%3}, {%4,%5,%6,%7}, {%8,%9}, {%0,%1,%2,%3};"
                 : "+f"(c[0]), "+f"(c[1]), "+f"(c[2]), "+f"(c[3])
                 : "r"(a[0]), "r"(a[1]), "r"(a[2]), "r"(a[3]), "r"(b[0]), "r"(b[1]));
}
__device__ __forceinline__ void pack2(float a, float b, uint32_t& h, uint32_t& l) {
    uint32_t hh;
    asm("cvt.rn.bf16x2.f32 %0, %1, %2;" : "=r"(hh) : "f"(b), "f"(a));
    float ra = a - __uint_as_float(hh << 16);
    float rb = b - __uint_as_float(hh & 0xffff0000u);
    uint32_t ll;
    asm("cvt.rn.bf16x2.f32 %0, %1, %2;" : "=r"(ll) : "f"(rb), "f"(ra));
    h = hh; l = ll;
}

// 64x128 fp32 tile -> bf16 hi/lo smem; LDG.128 + STS.64
__device__ __forceinline__ void cvt_tile(const float* __restrict__ src,
                                         char* hi, char* lo, int tid) {
#pragma unroll
    for (int it = 0; it < 8; ++it) {
        int n4  = tid + it * NTH;          // float4 index 0..2047
        int row = n4 >> 5, c4 = (n4 & 31) << 2;
        float4 x = ((const float4*)src)[n4];
        uint32_t h0, l0, h1, l1;
        pack2(x.x, x.y, h0, l0);
        pack2(x.z, x.w, h1, l1);
        *(uint2*)(hi + row * PITCHB + c4 * 2) = make_uint2(h0, h1);
        *(uint2*)(lo + row * PITCHB + c4 * 2) = make_uint2(l0, l1);
    }
}

__global__ __launch_bounds__(NTH, 2)
void qa_sp3_kernel(const float* __restrict__ q,
                   const float* __restrict__ k,
                   const float* __restrict__ v,
                   const int* __restrict__ mask,
                   float* __restrict__ out,
                   float* __restrict__ p)
{
    extern __shared__ char smem[];
    const uint32_t sb = smem_u32(smem);
    const int tid = threadIdx.x;
    const int lane = tid & 31, wid = tid >> 5;
    const int g = lane >> 2, tg = lane & 3;
    const int warpM = wid >> 2, warpN = wid & 3;
    const int b = blockIdx.y, qbase = blockIdx.x * TQ;

    const float* qb = q + ((size_t)b * SS + qbase) * DD;
    const float* kb = k + (size_t)b * SS * DD;
    const float* vb = v + (size_t)b * SS * DD;
    const int*   mk = mask + ((size_t)b * SS + qbase) * SS;
    float*       pb = p + ((size_t)b * SS + qbase) * SP1;
    float*       ob = out + ((size_t)b * SS + qbase) * DD;

    uint32_t* mbits = (uint32_t*)(smem + OFF_MB);
    float* redM = (float*)(smem + OFF_RM);
    float* redZ = (float*)(smem + OFF_RZ);
    float* sInv = (float*)(smem + OFF_SI);

    const uint32_t a_off  = (uint32_t)((((lane >> 3) & 1) * 8 + (lane & 7)) * PITCHB + (lane >> 4) * 16);
    const uint32_t b_off  = (uint32_t)(((lane >> 4) * 8 + (lane & 7)) * PITCHB + ((lane >> 3) & 1) * 16);
    const uint32_t a_offP = (uint32_t)((((lane >> 3) & 1) * 8 + (lane & 7)) * PITCHP + (lane >> 4) * 16);

    const float scale = 0.08838834764831845f;

    cvt_tile(qb, smem + OFF_QHI, smem + OFF_QLO, tid);
    pf_l2((const char*)kb + tid * 128);
    pf_l2((const char*)vb + tid * 128);
    pf_l2((const char*)(mk + (size_t)(tid >> 2) * SS + (tid & 3) * 16));

    float m_run[4], z_run[4];
#pragma unroll
    for (int i = 0; i < 4; ++i) { m_run[i] = -1e9f; z_run[i] = 0.0f; }

    float oacc[2][4][4];
#pragma unroll
    for (int mt = 0; mt < 2; ++mt)
#pragma unroll
        for (int nt = 0; nt < 4; ++nt)
#pragma unroll
            for (int e = 0; e < 4; ++e) oacc[mt][nt][e] = 0.0f;

    for (int kt = 0; kt < 32; ++kt) {
        __syncthreads();
        cvt_tile(kb + (size_t)kt * TK * DD, smem + OFF_KHI, smem + OFF_KLO, tid);
        cvt_tile(vb + (size_t)kt * TK * DD, smem + OFF_VHI, smem + OFF_VLO, tid);
        {
            const int* mkt = mk + kt * TK;
#pragma unroll 4
            for (int it = 0; it < 16; ++it) {
                int n = tid + it * NTH;
                int row = n >> 6, col = n & 63;
                int mval = mkt[(size_t)row * SS + col];
                unsigned bits = __ballot_sync(0xffffffffu, mval != 0);
                if (lane == 0) mbits[row * 2 + (col >> 5)] = bits;
            }
        }
        __syncthreads();

        if (kt + 1 < 32) {
            pf_l2((const char*)(kb + (size_t)(kt + 1) * TK * DD) + tid * 128);
            pf_l2((const char*)(vb + (size_t)(kt + 1) * TK * DD) + tid * 128);
            pf_l2((const char*)(mk + (size_t)(tid >> 2) * SS + (kt + 1) * TK + (tid & 3) * 16));
        }

        // ---- S = Q K^T: ks-outer, fragments loaded once, 3 split-MMAs ----
        float sacc[2][2][4];
#pragma unroll
        for (int mt = 0; mt < 2; ++mt)
#pragma unroll
            for (int nt = 0; nt < 2; ++nt)
#pragma unroll
                for (int e = 0; e < 4; ++e) sacc[mt][nt][e] = 0.0f;

#pragma unroll
        for (int ks = 0; ks < 8; ++ks) {
            uint32_t ah[2][4], al[2][4], bh[4], bl[4];
#pragma unroll
            for (int mt = 0; mt < 2; ++mt) {
                uint32_t ra = (uint32_t)((warpM * 32 + mt * 16) * PITCHB + ks * 32) + a_off;
                ldsm4(ah[mt], sb + OFF_QHI + ra);
                ldsm4(al[mt], sb + OFF_QLO + ra);
            }
            {
                uint32_t rb = (uint32_t)((warpN * 16) * PITCHB + ks * 32) + b_off;
                ldsm4(bh, sb + OFF_KHI + rb);
                ldsm4(bl, sb + OFF_KLO + rb);
            }
#pragma unroll
            for (int mt = 0; mt < 2; ++mt)
#pragma unroll
                for (int nt = 0; nt < 2; ++nt) {
                    mma16816(sacc[mt][nt], ah[mt], &bh[nt * 2]);   // hh
                    mma16816(sacc[mt][nt], ah[mt], &bl[nt * 2]);   // hl
                    mma16816(sacc[mt][nt], al[mt], &bh[nt * 2]);   // lh
                }
        }

        // ---- epilogue: e = exp(s) masked, track m & Z, write e ----
#pragma unroll
        for (int mt = 0; mt < 2; ++mt) {
#pragma unroll
            for (int rh = 0; rh < 2; ++rh) {
                const int i = mt * 2 + rh;
                const int row = warpM * 32 + mt * 16 + rh * 8 + g;
                const uint32_t mw = mbits[row * 2 + (warpN >> 1)];
                float* dst = pb + (size_t)row * SP1 + 1 + kt * TK + warpN * 16;
#pragma unroll
                for (int nt = 0; nt < 2; ++nt) {
#pragma unroll
                    for (int e = 0; e < 2; ++e) {
                        float s = sacc[mt][nt][rh * 2 + e] * scale;
                        int bit = (warpN & 1) * 16 + nt * 8 + tg * 2 + e;
                        bool um = (mw >> bit) & 1u;
                        float ev = um ? __expf(s) : 0.0f;
                        m_run[i] = fmaxf(m_run[i], um ? s : -1e9f);
                        z_run[i] += ev;
                        sacc[mt][nt][rh * 2 + e] = ev;
                        dst[nt * 8 + tg * 2 + e] = ev;
                    }
                }
            }
        }

        __syncthreads();   // K smem reads done -> reuse as P
        {
            char* phi = smem + OFF_KHI;
            char* plo = smem + OFF_KLO;
#pragma unroll
            for (int mt = 0; mt < 2; ++mt)
#pragma unroll
                for (int rh = 0; rh < 2; ++rh) {
                    const int row = warpM * 32 + mt * 16 + rh * 8 + g;
#pragma unroll
                    for (int nt = 0; nt < 2; ++nt) {
                        uint32_t h, l;
                        pack2(sacc[mt][nt][rh * 2], sacc[mt][nt][rh * 2 + 1], h, l);
                        const int col = warpN * 16 + nt * 8 + tg * 2;
                        *(uint32_t*)(phi + row * PITCHP + col * 2) = h;
                        *(uint32_t*)(plo + row * PITCHP + col * 2) = l;
                    }
                }
        }
        __syncthreads();

        // ---- O += P V: ks-outer fragment reuse ----
#pragma unroll
        for (int ks = 0; ks < 4; ++ks) {
            uint32_t ah[2][4], al[2][4], bh[2][4], bl[2][4];
#pragma unroll
            for (int mt = 0; mt < 2; ++mt) {
                uint32_t ra = (uint32_t)((warpM * 32 + mt * 16) * PITCHP + ks * 32) + a_offP;
                ldsm4(ah[mt], sb + OFF_KHI + ra);
                ldsm4(al[mt], sb + OFF_KLO + ra);
            }
#pragma unroll
            for (int n2 = 0; n2 < 2; ++n2) {
                uint32_t rb = (uint32_t)((ks * 16) * PITCHB + (warpN * 32 + n2 * 16) * 2) + a_off;
                ldsm4t(bh[n2], sb + OFF_VHI + rb);
                ldsm4t(bl[n2], sb + OFF_VLO + rb);
            }
#pragma unroll
            for (int mt = 0; mt < 2; ++mt)
#pragma unroll
                for (int nt = 0; nt < 4; ++nt) {
                    mma16816(oacc[mt][nt], ah[mt], &bh[nt >> 1][(nt & 1) * 2]);  // hh
                    mma16816(oacc[mt][nt], ah[mt], &bl[nt >> 1][(nt & 1) * 2]);  // hl
                    mma16816(oacc[mt][nt], al[mt], &bh[nt >> 1][(nt & 1) * 2]);  // lh
                }
        }
    }

    // ---- reduce m (max) and Z (sum) ----
#pragma unroll
    for (int off = 1; off <= 2; off <<= 1) {
#pragma unroll
        for (int i = 0; i < 4; ++i) {
            m_run[i] = fmaxf(m_run[i], __shfl_xor_sync(0xffffffffu, m_run[i], off));
            z_run[i] += __shfl_xor_sync(0xffffffffu, z_run[i], off);
        }
    }
    __syncthreads();
    if (tg == 0) {
#pragma unroll
        for (int i = 0; i < 4; ++i) {
            int row = warpM * 32 + (i >> 1) * 16 + (i & 1) * 8 + g;
            redM[warpN * 64 + row] = m_run[i];
            redZ[warpN * 64 + row] = z_run[i];
        }
    }
    __syncthreads();
    if (tid < 64) {
        float m = redM[tid], z = redZ[tid];
#pragma unroll
        for (int w = 1; w < 4; ++w) {
            m = fmaxf(m, redM[w * 64 + tid]);
            z += redZ[w * 64 + tid];
        }
        float inv = 1.0f / (__expf(m) + z);
        sInv[tid] = inv;
        pb[(size_t)tid * SP1] = 0.0f;
    }
    __syncthreads();

    // ---- write O (scaled) ----
#pragma unroll
    for (int mt = 0; mt < 2; ++mt)
#pragma unroll
        for (int rh = 0; rh < 2; ++rh) {
            int row = warpM * 32 + mt * 16 + rh * 8 + g;
            float inv = sInv[row];
#pragma unroll
            for (int nt = 0; nt < 4; ++nt) {
                int col = warpN * 32 + nt * 8 + tg * 2;
                float2 val = make_float2(oacc[mt][nt][rh * 2] * inv,
                                         oacc[mt][nt][rh * 2 + 1] * inv);
                *(float2*)(ob + (size_t)row * DD + col) = val;
            }
        }

    // ---- rescale p ----
    {
#pragma unroll 1
        for (int rr = 0; rr < 8; ++rr) {
            int row = wid * 8 + rr;
            float inv = sInv[row];
            float* ga = pb + (size_t)row * SP1 + 1;
#pragma unroll 8
            for (int c = lane; c < SS; c += 32)
                ga[c] *= inv;
        }
    }
}

extern "C" void kernel_launch(void* const* d_in, const int* in_sizes, int n_in,
                              void* d_out, int out_size)
{
    const float* q    = (const float*)d_in[0];
    const float* k    = (const float*)d_in[1];
    const float* v    = (const float*)d_in[2];
    const int*   mask = (const int*)d_in[3];

    const long OUT_N = (long)BB * SS * DD;
    const long P_N   = (long)BB * SS * SP1;

    float* out = (float*)d_out;
    float* p   = ((long)out_size == P_N) ? out : out + OUT_N;

    cudaFuncSetAttribute(qa_sp3_kernel,
                         cudaFuncAttributeMaxDynamicSharedMemorySize, SMEM_TOTAL);
    dim3 grid(SS / TQ, BB);
    qa_sp3_kernel<<<grid, NTH, SMEM_TOTAL>>>(q, k, v, mask, out, p);
}

// round 9
// speedup vs baseline: 1.4308x; 1.4308x over previous
#include <cuda_runtime.h>
#include <cstdint>

// QuietAttention, single-pass unnormalized softmax, TQ=64/TK=64,
// 256 threads, 2 CTAs/SM. Fragment-reuse ldmatrix (load once per ks) with
// split-outer MMA ordering (independent accumulators between same-reg issues).
// out [16,2048,128] fp32 then p_attn [16,2048,2049] fp32 in d_out.

#define BB 16
#define SS 2048
#define DD 128
#define SP1 2049
#define NTH 256
#define TQ 64
#define TK 64
#define PITCHB 272
#define PITCHP 144

#define OFF_QHI 0
#define OFF_QLO 17408
#define OFF_KHI 34816           // after QK: P hi
#define OFF_KLO 52224           // after QK: P lo
#define OFF_VHI 69632
#define OFF_VLO 87040
#define OFF_MB  104448
#define OFF_RM  104960
#define OFF_RZ  105984
#define OFF_SI  107008
#define SMEM_TOTAL 107264

__device__ __forceinline__ uint32_t smem_u32(const void* p) {
    uint32_t a;
    asm("{ .reg .u64 t; cvta.to.shared.u64 t, %1; cvt.u32.u64 %0, t; }" : "=r"(a) : "l"(p));
    return a;
}
__device__ __forceinline__ void pf_l2(const void* p) {
    asm volatile("prefetch.global.L2 [%0];" :: "l"(p));
}
__device__ __forceinline__ void ldsm4(uint32_t* r, uint32_t addr) {
    asm volatile("ldmatrix.sync.aligned.m8n8.x4.shared.b16 {%0,%1,%2,%3}, [%4];"
                 : "=r"(r[0]), "=r"(r[1]), "=r"(r[2]), "=r"(r[3]) : "r"(addr));
}
__device__ __forceinline__ void ldsm4t(uint32_t* r, uint32_t addr) {
    asm volatile("ldmatrix.sync.aligned.m8n8.x4.trans.shared.b16 {%0,%1,%2,%3}, [%4];"
                 : "=r"(r[0]), "=r"(r[1]), "=r"(r[2]), "=r"(r[3]) : "r"(addr));
}
__device__ __forceinline__ void mma16816(float* c, const uint32_t* a, const uint32_t* b) {
    asm volatile("mma.sync.aligned.m16n8k16.row.col.f32.bf16.bf16.f32 "
                 "{%0,%1,%2,%3}, {%4,%5,%6,%7}, {%8,%9}, {%0,%1,%2,%3};"
                 : "+f"(c[0]), "+f"(c[1]), "+f"(c[2]), "+f"(c[3])
                 : "r"(a[0]), "r"(a[1]), "r"(a[2]), "r"(a[3]), "r"(b[0]), "r"(b[1]));
}
__device__ __forceinline__ void pack2(float a, float b, uint32_t& h, uint32_t& l) {
    uint32_t hh;
    asm("cvt.rn.bf16x2.f32 %0, %1, %2;" : "=r"(hh) : "f"(b), "f"(a));
    float ra = a - __uint_as_float(hh << 16);
    float rb = b - __uint_as_float(hh & 0xffff0000u);
    uint32_t ll;
    asm("cvt.rn.bf16x2.f32 %0, %1, %2;" : "=r"(ll) : "f"(rb), "f"(ra));
    h = hh; l = ll;
}

// 64x128 fp32 tile -> bf16 hi/lo smem; LDG.128 + STS.64
__device__ __forceinline__ void cvt_tile(const float* __restrict__ src,
                                         char* hi, char* lo, int tid) {
#pragma unroll
    for (int it = 0; it < 8; ++it) {
        int n4  = tid + it * NTH;
        int row = n4 >> 5, c4 = (n4 & 31) << 2;
        float4 x = ((const float4*)src)[n4];
        uint32_t h0, l0, h1, l1;
        pack2(x.x, x.y, h0, l0);
        pack2(x.z, x.w, h1, l1);
        *(uint2*)(hi + row * PITCHB + c4 * 2) = make_uint2(h0, h1);
        *(uint2*)(lo + row * PITCHB + c4 * 2) = make_uint2(l0, l1);
    }
}

__global__ __launch_bounds__(NTH, 2)
void qa_sp4_kernel(const float* __restrict__ q,
                   const float* __restrict__ k,
                   const float* __restrict__ v,
                   const int* __restrict__ mask,
                   float* __restrict__ out,
                   float* __restrict__ p)
{
    extern __shared__ char smem[];
    const uint32_t sb = smem_u32(smem);
    const int tid = threadIdx.x;
    const int lane = tid & 31, wid = tid >> 5;
    const int g = lane >> 2, tg = lane & 3;
    const int warpM = wid >> 2, warpN = wid & 3;
    const int b = blockIdx.y, qbase = blockIdx.x * TQ;

    const float* qb = q + ((size_t)b * SS + qbase) * DD;
    const float* kb = k + (size_t)b * SS * DD;
    const float* vb = v + (size_t)b * SS * DD;
    const int*   mk = mask + ((size_t)b * SS + qbase) * SS;
    float*       pb = p + ((size_t)b * SS + qbase) * SP1;
    float*       ob = out + ((size_t)b * SS + qbase) * DD;

    uint32_t* mbits = (uint32_t*)(smem + OFF_MB);
    float* redM = (float*)(smem + OFF_RM);
    float* redZ = (float*)(smem + OFF_RZ);
    float* sInv = (float*)(smem + OFF_SI);

    const uint32_t a_off  = (uint32_t)((((lane >> 3) & 1) * 8 + (lane & 7)) * PITCHB + (lane >> 4) * 16);
    const uint32_t b_off  = (uint32_t)(((lane >> 4) * 8 + (lane & 7)) * PITCHB + ((lane >> 3) & 1) * 16);
    const uint32_t a_offP = (uint32_t)((((lane >> 3) & 1) * 8 + (lane & 7)) * PITCHP + (lane >> 4) * 16);

    const float scale = 0.08838834764831845f;

    cvt_tile(qb, smem + OFF_QHI, smem + OFF_QLO, tid);
    pf_l2((const char*)kb + tid * 128);
    pf_l2((const char*)vb + tid * 128);
    pf_l2((const char*)(mk + (size_t)(tid >> 2) * SS + (tid & 3) * 16));

    float m_run[4], z_run[4];
#pragma unroll
    for (int i = 0; i < 4; ++i) { m_run[i] = -1e9f; z_run[i] = 0.0f; }

    float oacc[2][4][4];
#pragma unroll
    for (int mt = 0; mt < 2; ++mt)
#pragma unroll
        for (int nt = 0; nt < 4; ++nt)
#pragma unroll
            for (int e = 0; e < 4; ++e) oacc[mt][nt][e] = 0.0f;

    for (int kt = 0; kt < 32; ++kt) {
        __syncthreads();
        cvt_tile(kb + (size_t)kt * TK * DD, smem + OFF_KHI, smem + OFF_KLO, tid);
        cvt_tile(vb + (size_t)kt * TK * DD, smem + OFF_VHI, smem + OFF_VLO, tid);
        {
            const int* mkt = mk + kt * TK;
#pragma unroll 4
            for (int it = 0; it < 16; ++it) {
                int n = tid + it * NTH;
                int row = n >> 6, col = n & 63;
                int mval = mkt[(size_t)row * SS + col];
                unsigned bits = __ballot_sync(0xffffffffu, mval != 0);
                if (lane == 0) mbits[row * 2 + (col >> 5)] = bits;
            }
        }
        __syncthreads();

        if (kt + 1 < 32) {
            pf_l2((const char*)(kb + (size_t)(kt + 1) * TK * DD) + tid * 128);
            pf_l2((const char*)(vb + (size_t)(kt + 1) * TK * DD) + tid * 128);
            pf_l2((const char*)(mk + (size_t)(tid >> 2) * SS + (kt + 1) * TK + (tid & 3) * 16));
        }

        // ---- S = Q K^T: fragments once per ks; split-outer MMA order ----
        float sacc[2][2][4];
#pragma unroll
        for (int mt = 0; mt < 2; ++mt)
#pragma unroll
            for (int nt = 0; nt < 2; ++nt)
#pragma unroll
                for (int e = 0; e < 4; ++e) sacc[mt][nt][e] = 0.0f;

#pragma unroll
        for (int ks = 0; ks < 8; ++ks) {
            uint32_t ah[2][4], al[2][4], bh[4], bl[4];
#pragma unroll
            for (int mt = 0; mt < 2; ++mt) {
                uint32_t ra = (uint32_t)((warpM * 32 + mt * 16) * PITCHB + ks * 32) + a_off;
                ldsm4(ah[mt], sb + OFF_QHI + ra);
                ldsm4(al[mt], sb + OFF_QLO + ra);
            }
            {
                uint32_t rb = (uint32_t)((warpN * 16) * PITCHB + ks * 32) + b_off;
                ldsm4(bh, sb + OFF_KHI + rb);
                ldsm4(bl, sb + OFF_KLO + rb);
            }
            // split-outer: 4 independent accumulators between same-reg issues
#pragma unroll
            for (int mt = 0; mt < 2; ++mt)
#pragma unroll
                for (int nt = 0; nt < 2; ++nt)
                    mma16816(sacc[mt][nt], ah[mt], &bh[nt * 2]);   // hh
#pragma unroll
            for (int mt = 0; mt < 2; ++mt)
#pragma unroll
                for (int nt = 0; nt < 2; ++nt)
                    mma16816(sacc[mt][nt], ah[mt], &bl[nt * 2]);   // hl
#pragma unroll
            for (int mt = 0; mt < 2; ++mt)
#pragma unroll
                for (int nt = 0; nt < 2; ++nt)
                    mma16816(sacc[mt][nt], al[mt], &bh[nt * 2]);   // lh
        }

        // ---- epilogue: e = exp(s) masked, track m & Z, write e ----
#pragma unroll
        for (int mt = 0; mt < 2; ++mt) {
#pragma unroll
            for (int rh = 0; rh < 2; ++rh) {
                const int i = mt * 2 + rh;
                const int row = warpM * 32 + mt * 16 + rh * 8 + g;
                const uint32_t mw = mbits[row * 2 + (warpN >> 1)];
                float* dst = pb + (size_t)row * SP1 + 1 + kt * TK + warpN * 16;
#pragma unroll
                for (int nt = 0; nt < 2; ++nt) {
#pragma unroll
                    for (int e = 0; e < 2; ++e) {
                        float s = sacc[mt][nt][rh * 2 + e] * scale;
                        int bit = (warpN & 1) * 16 + nt * 8 + tg * 2 + e;
                        bool um = (mw >> bit) & 1u;
                        float ev = um ? __expf(s) : 0.0f;
                        m_run[i] = fmaxf(m_run[i], um ? s : -1e9f);
                        z_run[i] += ev;
                        sacc[mt][nt][rh * 2 + e] = ev;
                        dst[nt * 8 + tg * 2 + e] = ev;
                    }
                }
            }
        }

        __syncthreads();   // K smem reads done -> reuse as P
        {
            char* phi = smem + OFF_KHI;
            char* plo = smem + OFF_KLO;
#pragma unroll
            for (int mt = 0; mt < 2; ++mt)
#pragma unroll
                for (int rh = 0; rh < 2; ++rh) {
                    const int row = warpM * 32 + mt * 16 + rh * 8 + g;
#pragma unroll
                    for (int nt = 0; nt < 2; ++nt) {
                        uint32_t h, l;
                        pack2(sacc[mt][nt][rh * 2], sacc[mt][nt][rh * 2 + 1], h, l);
                        const int col = warpN * 16 + nt * 8 + tg * 2;
                        *(uint32_t*)(phi + row * PITCHP + col * 2) = h;
                        *(uint32_t*)(plo + row * PITCHP + col * 2) = l;
                    }
                }
        }
        __syncthreads();

        // ---- O += P V: fragments once per ks; split-outer order ----
#pragma unroll
        for (int ks = 0; ks < 4; ++ks) {
            uint32_t ah[2][4], al[2][4], bh[2][4], bl[2][4];
#pragma unroll
            for (int mt = 0; mt < 2; ++mt) {
                uint32_t ra = (uint32_t)((warpM * 32 + mt * 16) * PITCHP + ks * 32) + a_offP;
                ldsm4(ah[mt], sb + OFF_KHI + ra);
                ldsm4(al[mt], sb + OFF_KLO + ra);
            }
#pragma unroll
            for (int n2 = 0; n2 < 2; ++n2) {
                uint32_t rb = (uint32_t)((ks * 16) * PITCHB + (warpN * 32 + n2 * 16) * 2) + a_off;
                ldsm4t(bh[n2], sb + OFF_VHI + rb);
                ldsm4t(bl[n2], sb + OFF_VLO + rb);
            }
            // split-outer: 8 independent accumulators between same-reg issues
#pragma unroll
            for (int mt = 0; mt < 2; ++mt)
#pragma unroll
                for (int nt = 0; nt < 4; ++nt)
                    mma16816(oacc[mt][nt], ah[mt], &bh[nt >> 1][(nt & 1) * 2]);  // hh
#pragma unroll
            for (int mt = 0; mt < 2; ++mt)
#pragma unroll
                for (int nt = 0; nt < 4; ++nt)
                    mma16816(oacc[mt][nt], ah[mt], &bl[nt >> 1][(nt & 1) * 2]);  // hl
#pragma unroll
            for (int mt = 0; mt < 2; ++mt)
#pragma unroll
                for (int nt = 0; nt < 4; ++nt)
                    mma16816(oacc[mt][nt], al[mt], &bh[nt >> 1][(nt & 1) * 2]);  // lh
        }
    }

    // ---- reduce m (max) and Z (sum) ----
#pragma unroll
    for (int off = 1; off <= 2; off <<= 1) {
#pragma unroll
        for (int i = 0; i < 4; ++i) {
            m_run[i] = fmaxf(m_run[i], __shfl_xor_sync(0xffffffffu, m_run[i], off));
            z_run[i] += __shfl_xor_sync(0xffffffffu, z_run[i], off);
        }
    }
    __syncthreads();
    if (tg == 0) {
#pragma unroll
        for (int i = 0; i < 4; ++i) {
            int row = warpM * 32 + (i >> 1) * 16 + (i & 1) * 8 + g;
            redM[warpN * 64 + row] = m_run[i];
            redZ[warpN * 64 + row] = z_run[i];
        }
    }
    __syncthreads();
    if (tid < 64) {
        float m = redM[tid], z = redZ[tid];
#pragma unroll
        for (int w = 1; w < 4; ++w) {
            m = fmaxf(m, redM[w * 64 + tid]);
            z += redZ[w * 64 + tid];
        }
        float inv = 1.0f / (__expf(m) + z);
        sInv[tid] = inv;
        pb[(size_t)tid * SP1] = 0.0f;
    }
    __syncthreads();

    // ---- write O (scaled) ----
#pragma unroll
    for (int mt = 0; mt < 2; ++mt)
#pragma unroll
        for (int rh = 0; rh < 2; ++rh) {
            int row = warpM * 32 + mt * 16 + rh * 8 + g;
            float inv = sInv[row];
#pragma unroll
            for (int nt = 0; nt < 4; ++nt) {
                int col = warpN * 32 + nt * 8 + tg * 2;
                float2 val = make_float2(oacc[mt][nt][rh * 2] * inv,
                                         oacc[mt][nt][rh * 2 + 1] * inv);
                *(float2*)(ob + (size_t)row * DD + col) = val;
            }
        }

    // ---- rescale p ----
    {
#pragma unroll 1
        for (int rr = 0; rr < 8; ++rr) {
            int row = wid * 8 + rr;
            float inv = sInv[row];
            float* ga = pb + (size_t)row * SP1 + 1;
#pragma unroll 8
            for (int c = lane; c < SS; c += 32)
                ga[c] *= inv;
        }
    }
}

extern "C" void kernel_launch(void* const* d_in, const int* in_sizes, int n_in,
                              void* d_out, int out_size)
{
    const float* q    = (const float*)d_in[0];
    const float* k    = (const float*)d_in[1];
    const float* v    = (const float*)d_in[2];
    const int*   mask = (const int*)d_in[3];

    const long OUT_N = (long)BB * SS * DD;
    const long P_N   = (long)BB * SS * SP1;

    float* out = (float*)d_out;
    float* p   = ((long)out_size == P_N) ? out : out + OUT_N;

    cudaFuncSetAttribute(qa_sp4_kernel,
                         cudaFuncAttributeMaxDynamicSharedMemorySize, SMEM_TOTAL);
    dim3 grid(SS / TQ, BB);
    qa_sp4_kernel<<<grid, NTH, SMEM_TOTAL>>>(q, k, v, mask, out, p);
}

// round 10
// speedup vs baseline: 1.4658x; 1.0245x over previous
#include <cuda_runtime.h>
#include <cstdint>

// QuietAttention, single-pass unnormalized softmax, TQ=64/TK=64,
// 256 threads, 2 CTAs/SM, fragment-reuse + split-outer MMA order,
// e-store overlapped with PV, vectorized rescale tail, streaming hints.
// out [16,2048,128] fp32 then p_attn [16,2048,2049] fp32 in d_out.

#define BB 16
#define SS 2048
#define DD 128
#define SP1 2049
#define NTH 256
#define TQ 64
#define TK 64
#define PITCHB 272
#define PITCHP 144

#define OFF_QHI 0
#define OFF_QLO 17408
#define OFF_KHI 34816           // after QK: P hi
#define OFF_KLO 52224           // after QK: P lo
#define OFF_VHI 69632
#define OFF_VLO 87040
#define OFF_MB  104448
#define OFF_RM  104960
#define OFF_RZ  105984
#define OFF_SI  107008
#define SMEM_TOTAL 107264

__device__ __forceinline__ uint32_t smem_u32(const void* p) {
    uint32_t a;
    asm("{ .reg .u64 t; cvta.to.shared.u64 t, %1; cvt.u32.u64 %0, t; }" : "=r"(a) : "l"(p));
    return a;
}
__device__ __forceinline__ void pf_l2(const void* p) {
    asm volatile("prefetch.global.L2 [%0];" :: "l"(p));
}
__device__ __forceinline__ void ldsm4(uint32_t* r, uint32_t addr) {
    asm volatile("ldmatrix.sync.aligned.m8n8.x4.shared.b16 {%0,%1,%2,%3}, [%4];"
                 : "=r"(r[0]), "=r"(r[1]), "=r"(r[2]), "=r"(r[3]) : "r"(addr));
}
__device__ __forceinline__ void ldsm4t(uint32_t* r, uint32_t addr) {
    asm volatile("ldmatrix.sync.aligned.m8n8.x4.trans.shared.b16 {%0,%1,%2,%3}, [%4];"
                 : "=r"(r[0]), "=r"(r[1]), "=r"(r[2]), "=r"(r[3]) : "r"(addr));
}
__device__ __forceinline__ void mma16816(float* c, const uint32_t* a, const uint32_t* b) {
    asm volatile("mma.sync.aligned.m16n8k16.row.col.f32.bf16.bf16.f32 "
                 "{%0,%1,%2,%3}, {%4,%5,%6,%7}, {%8,%9}, {%0,%1,%2,%3};"
                 : "+f"(c[0]), "+f"(c[1]), "+f"(c[2]), "+f"(c[3])
                 : "r"(a[0]), "r"(a[1]), "r"(a[2]), "r"(a[3]), "r"(b[0]), "r"(b[1]));
}
__device__ __forceinline__ void pack2(float a, float b, uint32_t& h, uint32_t& l) {
    uint32_t hh;
    asm("cvt.rn.bf16x2.f32 %0, %1, %2;" : "=r"(hh) : "f"(b), "f"(a));
    float ra = a - __uint_as_float(hh << 16);
    float rb = b - __uint_as_float(hh & 0xffff0000u);
    uint32_t ll;
    asm("cvt.rn.bf16x2.f32 %0, %1, %2;" : "=r"(ll) : "f"(rb), "f"(ra));
    h = hh; l = ll;
}

// 64x128 fp32 tile -> bf16 hi/lo smem; LDG.128 + STS.64
__device__ __forceinline__ void cvt_tile(const float* __restrict__ src,
                                         char* hi, char* lo, int tid) {
#pragma unroll
    for (int it = 0; it < 8; ++it) {
        int n4  = tid + it * NTH;
        int row = n4 >> 5, c4 = (n4 & 31) << 2;
        float4 x = ((const float4*)src)[n4];
        uint32_t h0, l0, h1, l1;
        pack2(x.x, x.y, h0, l0);
        pack2(x.z, x.w, h1, l1);
        *(uint2*)(hi + row * PITCHB + c4 * 2) = make_uint2(h0, h1);
        *(uint2*)(lo + row * PITCHB + c4 * 2) = make_uint2(l0, l1);
    }
}

__global__ __launch_bounds__(NTH, 2)
void qa_sp5_kernel(const float* __restrict__ q,
                   const float* __restrict__ k,
                   const float* __restrict__ v,
                   const int* __restrict__ mask,
                   float* __restrict__ out,
                   float* __restrict__ p)
{
    extern __shared__ char smem[];
    const uint32_t sb = smem_u32(smem);
    const int tid = threadIdx.x;
    const int lane = tid & 31, wid = tid >> 5;
    const int g = lane >> 2, tg = lane & 3;
    const int warpM = wid >> 2, warpN = wid & 3;
    const int b = blockIdx.y, qbase = blockIdx.x * TQ;

    const float* qb = q + ((size_t)b * SS + qbase) * DD;
    const float* kb = k + (size_t)b * SS * DD;
    const float* vb = v + (size_t)b * SS * DD;
    const int*   mk = mask + ((size_t)b * SS + qbase) * SS;
    float*       pb = p + ((size_t)b * SS + qbase) * SP1;
    float*       ob = out + ((size_t)b * SS + qbase) * DD;

    uint32_t* mbits = (uint32_t*)(smem + OFF_MB);
    float* redM = (float*)(smem + OFF_RM);
    float* redZ = (float*)(smem + OFF_RZ);
    float* sInv = (float*)(smem + OFF_SI);

    const uint32_t a_off  = (uint32_t)((((lane >> 3) & 1) * 8 + (lane & 7)) * PITCHB + (lane >> 4) * 16);
    const uint32_t b_off  = (uint32_t)(((lane >> 4) * 8 + (lane & 7)) * PITCHB + ((lane >> 3) & 1) * 16);
    const uint32_t a_offP = (uint32_t)((((lane >> 3) & 1) * 8 + (lane & 7)) * PITCHP + (lane >> 4) * 16);

    const float scale = 0.08838834764831845f;

    cvt_tile(qb, smem + OFF_QHI, smem + OFF_QLO, tid);
    pf_l2((const char*)kb + tid * 128);
    pf_l2((const char*)vb + tid * 128);
    pf_l2((const char*)(mk + (size_t)(tid >> 2) * SS + (tid & 3) * 16));

    float m_run[4], z_run[4];
#pragma unroll
    for (int i = 0; i < 4; ++i) { m_run[i] = -1e9f; z_run[i] = 0.0f; }

    float oacc[2][4][4];
#pragma unroll
    for (int mt = 0; mt < 2; ++mt)
#pragma unroll
        for (int nt = 0; nt < 4; ++nt)
#pragma unroll
            for (int e = 0; e < 4; ++e) oacc[mt][nt][e] = 0.0f;

    for (int kt = 0; kt < 32; ++kt) {
        __syncthreads();
        cvt_tile(kb + (size_t)kt * TK * DD, smem + OFF_KHI, smem + OFF_KLO, tid);
        cvt_tile(vb + (size_t)kt * TK * DD, smem + OFF_VHI, smem + OFF_VLO, tid);
        {
            const int* mkt = mk + kt * TK;
#pragma unroll 4
            for (int it = 0; it < 16; ++it) {
                int n = tid + it * NTH;
                int row = n >> 6, col = n & 63;
                int mval = mkt[(size_t)row * SS + col];
                unsigned bits = __ballot_sync(0xffffffffu, mval != 0);
                if (lane == 0) mbits[row * 2 + (col >> 5)] = bits;
            }
        }
        __syncthreads();

        if (kt + 1 < 32) {
            pf_l2((const char*)(kb + (size_t)(kt + 1) * TK * DD) + tid * 128);
            pf_l2((const char*)(vb + (size_t)(kt + 1) * TK * DD) + tid * 128);
            pf_l2((const char*)(mk + (size_t)(tid >> 2) * SS + (kt + 1) * TK + (tid & 3) * 16));
        }

        // ---- S = Q K^T: fragments once per ks; split-outer MMA order ----
        float sacc[2][2][4];
#pragma unroll
        for (int mt = 0; mt < 2; ++mt)
#pragma unroll
            for (int nt = 0; nt < 2; ++nt)
#pragma unroll
                for (int e = 0; e < 4; ++e) sacc[mt][nt][e] = 0.0f;

#pragma unroll
        for (int ks = 0; ks < 8; ++ks) {
            uint32_t ah[2][4], al[2][4], bh[4], bl[4];
#pragma unroll
            for (int mt = 0; mt < 2; ++mt) {
                uint32_t ra = (uint32_t)((warpM * 32 + mt * 16) * PITCHB + ks * 32) + a_off;
                ldsm4(ah[mt], sb + OFF_QHI + ra);
                ldsm4(al[mt], sb + OFF_QLO + ra);
            }
            {
                uint32_t rb = (uint32_t)((warpN * 16) * PITCHB + ks * 32) + b_off;
                ldsm4(bh, sb + OFF_KHI + rb);
                ldsm4(bl, sb + OFF_KLO + rb);
            }
#pragma unroll
            for (int mt = 0; mt < 2; ++mt)
#pragma unroll
                for (int nt = 0; nt < 2; ++nt)
                    mma16816(sacc[mt][nt], ah[mt], &bh[nt * 2]);   // hh
#pragma unroll
            for (int mt = 0; mt < 2; ++mt)
#pragma unroll
                for (int nt = 0; nt < 2; ++nt)
                    mma16816(sacc[mt][nt], ah[mt], &bl[nt * 2]);   // hl
#pragma unroll
            for (int mt = 0; mt < 2; ++mt)
#pragma unroll
                for (int nt = 0; nt < 2; ++nt)
                    mma16816(sacc[mt][nt], al[mt], &bh[nt * 2]);   // lh
        }

        // ---- epilogue: e = exp(s) masked, track m & Z (no gmem store yet) ----
#pragma unroll
        for (int mt = 0; mt < 2; ++mt) {
#pragma unroll
            for (int rh = 0; rh < 2; ++rh) {
                const int i = mt * 2 + rh;
                const int row = warpM * 32 + mt * 16 + rh * 8 + g;
                const uint32_t mw = mbits[row * 2 + (warpN >> 1)];
#pragma unroll
                for (int nt = 0; nt < 2; ++nt) {
#pragma unroll
                    for (int e = 0; e < 2; ++e) {
                        float s = sacc[mt][nt][rh * 2 + e] * scale;
                        int bit = (warpN & 1) * 16 + nt * 8 + tg * 2 + e;
                        bool um = (mw >> bit) & 1u;
                        float ev = um ? __expf(s) : 0.0f;
                        m_run[i] = fmaxf(m_run[i], um ? s : -1e9f);
                        z_run[i] += ev;
                        sacc[mt][nt][rh * 2 + e] = ev;
                    }
                }
            }
        }

        __syncthreads();   // K smem reads done -> reuse as P
        {
            char* phi = smem + OFF_KHI;
            char* plo = smem + OFF_KLO;
#pragma unroll
            for (int mt = 0; mt < 2; ++mt)
#pragma unroll
                for (int rh = 0; rh < 2; ++rh) {
                    const int row = warpM * 32 + mt * 16 + rh * 8 + g;
#pragma unroll
                    for (int nt = 0; nt < 2; ++nt) {
                        uint32_t h, l;
                        pack2(sacc[mt][nt][rh * 2], sacc[mt][nt][rh * 2 + 1], h, l);
                        const int col = warpN * 16 + nt * 8 + tg * 2;
                        *(uint32_t*)(phi + row * PITCHP + col * 2) = h;
                        *(uint32_t*)(plo + row * PITCHP + col * 2) = l;
                    }
                }
        }
        __syncthreads();

        // ---- e-write to gmem (overlaps PV tensor phase; streaming hint) ----
#pragma unroll
        for (int mt = 0; mt < 2; ++mt)
#pragma unroll
            for (int rh = 0; rh < 2; ++rh) {
                const int row = warpM * 32 + mt * 16 + rh * 8 + g;
                float* dst = pb + (size_t)row * SP1 + 1 + kt * TK + warpN * 16;
#pragma unroll
                for (int nt = 0; nt < 2; ++nt) {
                    __stcs(dst + nt * 8 + tg * 2,     sacc[mt][nt][rh * 2]);
                    __stcs(dst + nt * 8 + tg * 2 + 1, sacc[mt][nt][rh * 2 + 1]);
                }
            }

        // ---- O += P V: fragments once per ks; split-outer order ----
#pragma unroll
        for (int ks = 0; ks < 4; ++ks) {
            uint32_t ah[2][4], al[2][4], bh[2][4], bl[2][4];
#pragma unroll
            for (int mt = 0; mt < 2; ++mt) {
                uint32_t ra = (uint32_t)((warpM * 32 + mt * 16) * PITCHP + ks * 32) + a_offP;
                ldsm4(ah[mt], sb + OFF_KHI + ra);
                ldsm4(al[mt], sb + OFF_KLO + ra);
            }
#pragma unroll
            for (int n2 = 0; n2 < 2; ++n2) {
                uint32_t rb = (uint32_t)((ks * 16) * PITCHB + (warpN * 32 + n2 * 16) * 2) + a_off;
                ldsm4t(bh[n2], sb + OFF_VHI + rb);
                ldsm4t(bl[n2], sb + OFF_VLO + rb);
            }
#pragma unroll
            for (int mt = 0; mt < 2; ++mt)
#pragma unroll
                for (int nt = 0; nt < 4; ++nt)
                    mma16816(oacc[mt][nt], ah[mt], &bh[nt >> 1][(nt & 1) * 2]);  // hh
#pragma unroll
            for (int mt = 0; mt < 2; ++mt)
#pragma unroll
                for (int nt = 0; nt < 4; ++nt)
                    mma16816(oacc[mt][nt], ah[mt], &bl[nt >> 1][(nt & 1) * 2]);  // hl
#pragma unroll
            for (int mt = 0; mt < 2; ++mt)
#pragma unroll
                for (int nt = 0; nt < 4; ++nt)
                    mma16816(oacc[mt][nt], al[mt], &bh[nt >> 1][(nt & 1) * 2]);  // lh
        }
    }

    // ---- reduce m (max) and Z (sum) ----
#pragma unroll
    for (int off = 1; off <= 2; off <<= 1) {
#pragma unroll
        for (int i = 0; i < 4; ++i) {
            m_run[i] = fmaxf(m_run[i], __shfl_xor_sync(0xffffffffu, m_run[i], off));
            z_run[i] += __shfl_xor_sync(0xffffffffu, z_run[i], off);
        }
    }
    __syncthreads();
    if (tg == 0) {
#pragma unroll
        for (int i = 0; i < 4; ++i) {
            int row = warpM * 32 + (i >> 1) * 16 + (i & 1) * 8 + g;
            redM[warpN * 64 + row] = m_run[i];
            redZ[warpN * 64 + row] = z_run[i];
        }
    }
    __syncthreads();
    if (tid < 64) {
        float m = redM[tid], z = redZ[tid];
#pragma unroll
        for (int w = 1; w < 4; ++w) {
            m = fmaxf(m, redM[w * 64 + tid]);
            z += redZ[w * 64 + tid];
        }
        float inv = 1.0f / (__expf(m) + z);
        sInv[tid] = inv;
        pb[(size_t)tid * SP1] = 0.0f;
    }
    __syncthreads();

    // ---- write O (scaled) ----
#pragma unroll
    for (int mt = 0; mt < 2; ++mt)
#pragma unroll
        for (int rh = 0; rh < 2; ++rh) {
            int row = warpM * 32 + mt * 16 + rh * 8 + g;
            float inv = sInv[row];
#pragma unroll
            for (int nt = 0; nt < 4; ++nt) {
                int col = warpN * 32 + nt * 8 + tg * 2;
                float2 val = make_float2(oacc[mt][nt][rh * 2] * inv,
                                         oacc[mt][nt][rh * 2 + 1] * inv);
                *(float2*)(ob + (size_t)row * DD + col) = val;
            }
        }

    // ---- rescale p: float4 body with alignment peel ----
    {
#pragma unroll 1
        for (int rr = 0; rr < 8; ++rr) {
            const int row = wid * 8 + rr;
            const float inv = sInv[row];
            float* ga = pb + (size_t)row * SP1 + 1;
            const int head = (4 - ((row * SP1 + 1) & 3)) & 3;   // floats to 16B align
            if (lane < head) ga[lane] *= inv;
            const int body4 = (SS - head) >> 2;
            float4* g4 = (float4*)(ga + head);
#pragma unroll 4
            for (int c = lane; c < body4; c += 32) {
                float4 x = __ldcs(g4 + c);
                x.x *= inv; x.y *= inv; x.z *= inv; x.w *= inv;
                __stcs(g4 + c, x);
            }
            const int done = head + body4 * 4;
            if (lane < (SS - done)) ga[done + lane] *= inv;
        }
    }
}

extern "C" void kernel_launch(void* const* d_in, const int* in_sizes, int n_in,
                              void* d_out, int out_size)
{
    const float* q    = (const float*)d_in[0];
    const float* k    = (const float*)d_in[1];
    const float* v    = (const float*)d_in[2];
    const int*   mask = (const int*)d_in[3];

    const long OUT_N = (long)BB * SS * DD;
    const long P_N   = (long)BB * SS * SP1;

    float* out = (float*)d_out;
    float* p   = ((long)out_size == P_N) ? out : out + OUT_N;

    cudaFuncSetAttribute(qa_sp5_kernel,
                         cudaFuncAttributeMaxDynamicSharedMemorySize, SMEM_TOTAL);
    dim3 grid(SS / TQ, BB);
    qa_sp5_kernel<<<grid, NTH, SMEM_TOTAL>>>(q, k, v, mask, out, p);
}

// round 11
// speedup vs baseline: 1.6206x; 1.1056x over previous
#include <cuda_runtime.h>
#include <cstdint>

// QuietAttention, single-pass unnormalized softmax, TQ=64/TK=64,
// 256 threads, 2 CTAs/SM. Fragment-reuse + split-outer MMA order,
// int4 mask bit-pack (no ballot), emax tracking, V-convert mid-iteration,
// e-store overlapped with PV, vectorized rescale tail, streaming hints.
// out [16,2048,128] fp32 then p_attn [16,2048,2049] fp32 in d_out.

#define BB 16
#define SS 2048
#define DD 128
#define SP1 2049
#define NTH 256
#define TQ 64
#define TK 64
#define PITCHB 272
#define PITCHP 144

#define OFF_QHI 0
#define OFF_QLO 17408
#define OFF_KHI 34816           // after QK: P hi
#define OFF_KLO 52224           // after QK: P lo
#define OFF_VHI 69632
#define OFF_VLO 87040
#define OFF_MB  104448          // uint16 mbits[64][4] = 512 B
#define OFF_RM  104960
#define OFF_RZ  105984
#define OFF_SI  107008
#define SMEM_TOTAL 107264

__device__ __forceinline__ uint32_t smem_u32(const void* p) {
    uint32_t a;
    asm("{ .reg .u64 t; cvta.to.shared.u64 t, %1; cvt.u32.u64 %0, t; }" : "=r"(a) : "l"(p));
    return a;
}
__device__ __forceinline__ void pf_l2(const void* p) {
    asm volatile("prefetch.global.L2 [%0];" :: "l"(p));
}
__device__ __forceinline__ void ldsm4(uint32_t* r, uint32_t addr) {
    asm volatile("ldmatrix.sync.aligned.m8n8.x4.shared.b16 {%0,%1,%2,%3}, [%4];"
                 : "=r"(r[0]), "=r"(r[1]), "=r"(r[2]), "=r"(r[3]) : "r"(addr));
}
__device__ __forceinline__ void ldsm4t(uint32_t* r, uint32_t addr) {
    asm volatile("ldmatrix.sync.aligned.m8n8.x4.trans.shared.b16 {%0,%1,%2,%3}, [%4];"
                 : "=r"(r[0]), "=r"(r[1]), "=r"(r[2]), "=r"(r[3]) : "r"(addr));
}
__device__ __forceinline__ void mma16816(float* c, const uint32_t* a, const uint32_t* b) {
    asm volatile("mma.sync.aligned.m16n8k16.row.col.f32.bf16.bf16.f32 "
                 "{%0,%1,%2,%3}, {%4,%5,%6,%7}, {%8,%9}, {%0,%1,%2,%3};"
                 : "+f"(c[0]), "+f"(c[1]), "+f"(c[2]), "+f"(c[3])
                 : "r"(a[0]), "r"(a[1]), "r"(a[2]), "r"(a[3]), "r"(b[0]), "r"(b[1]));
}
__device__ __forceinline__ void pack2(float a, float b, uint32_t& h, uint32_t& l) {
    uint32_t hh;
    asm("cvt.rn.bf16x2.f32 %0, %1, %2;" : "=r"(hh) : "f"(b), "f"(a));
    float ra = a - __uint_as_float(hh << 16);
    float rb = b - __uint_as_float(hh & 0xffff0000u);
    uint32_t ll;
    asm("cvt.rn.bf16x2.f32 %0, %1, %2;" : "=r"(ll) : "f"(rb), "f"(ra));
    h = hh; l = ll;
}

// 64x128 fp32 tile -> bf16 hi/lo smem; LDG.128 + STS.64
__device__ __forceinline__ void cvt_tile(const float* __restrict__ src,
                                         char* hi, char* lo, int tid) {
#pragma unroll
    for (int it = 0; it < 8; ++it) {
        int n4  = tid + it * NTH;
        int row = n4 >> 5, c4 = (n4 & 31) << 2;
        float4 x = ((const float4*)src)[n4];
        uint32_t h0, l0, h1, l1;
        pack2(x.x, x.y, h0, l0);
        pack2(x.z, x.w, h1, l1);
        *(uint2*)(hi + row * PITCHB + c4 * 2) = make_uint2(h0, h1);
        *(uint2*)(lo + row * PITCHB + c4 * 2) = make_uint2(l0, l1);
    }
}

__global__ __launch_bounds__(NTH, 2)
void qa_sp6_kernel(const float* __restrict__ q,
                   const float* __restrict__ k,
                   const float* __restrict__ v,
                   const int* __restrict__ mask,
                   float* __restrict__ out,
                   float* __restrict__ p)
{
    extern __shared__ char smem[];
    const uint32_t sb = smem_u32(smem);
    const int tid = threadIdx.x;
    const int lane = tid & 31, wid = tid >> 5;
    const int g = lane >> 2, tg = lane & 3;
    const int warpM = wid >> 2, warpN = wid & 3;
    const int b = blockIdx.y, qbase = blockIdx.x * TQ;

    const float* qb = q + ((size_t)b * SS + qbase) * DD;
    const float* kb = k + (size_t)b * SS * DD;
    const float* vb = v + (size_t)b * SS * DD;
    const int*   mk = mask + ((size_t)b * SS + qbase) * SS;
    float*       pb = p + ((size_t)b * SS + qbase) * SP1;
    float*       ob = out + ((size_t)b * SS + qbase) * DD;

    uint16_t* mbits = (uint16_t*)(smem + OFF_MB);
    float* redM = (float*)(smem + OFF_RM);
    float* redZ = (float*)(smem + OFF_RZ);
    float* sInv = (float*)(smem + OFF_SI);

    const uint32_t a_off  = (uint32_t)((((lane >> 3) & 1) * 8 + (lane & 7)) * PITCHB + (lane >> 4) * 16);
    const uint32_t b_off  = (uint32_t)(((lane >> 4) * 8 + (lane & 7)) * PITCHB + ((lane >> 3) & 1) * 16);
    const uint32_t a_offP = (uint32_t)((((lane >> 3) & 1) * 8 + (lane & 7)) * PITCHP + (lane >> 4) * 16);

    const float scale = 0.08838834764831845f;

    cvt_tile(qb, smem + OFF_QHI, smem + OFF_QLO, tid);
    pf_l2((const char*)kb + tid * 128);
    pf_l2((const char*)vb + tid * 128);
    pf_l2((const char*)(mk + (size_t)(tid >> 2) * SS + (tid & 3) * 16));

    // emax_run = max e^s over unmasked (== e^m), z_run = plain sum of e
    float emax_run[4], z_run[4];
#pragma unroll
    for (int i = 0; i < 4; ++i) { emax_run[i] = 0.0f; z_run[i] = 0.0f; }

    float oacc[2][4][4];
#pragma unroll
    for (int mt = 0; mt < 2; ++mt)
#pragma unroll
        for (int nt = 0; nt < 4; ++nt)
#pragma unroll
            for (int e = 0; e < 4; ++e) oacc[mt][nt][e] = 0.0f;

    for (int kt = 0; kt < 32; ++kt) {
        __syncthreads();                 // prior PV done with V & P smem
        // ---- head phase: K convert + mask bit-pack (V deferred) ----
        cvt_tile(kb + (size_t)kt * TK * DD, smem + OFF_KHI, smem + OFF_KLO, tid);
        {
            const int row = tid >> 2, cg = tid & 3;       // 64 rows x 4 groups
            const int4* mp = (const int4*)(mk + (size_t)row * SS + kt * TK + cg * 16);
            uint32_t bits = 0;
#pragma unroll
            for (int j = 0; j < 4; ++j) {
                int4 m4 = __ldcs(mp + j);
                bits |= (m4.x ? 1u : 0u) << (4 * j);
                bits |= (m4.y ? 1u : 0u) << (4 * j + 1);
                bits |= (m4.z ? 1u : 0u) << (4 * j + 2);
                bits |= (m4.w ? 1u : 0u) << (4 * j + 3);
            }
            mbits[row * 4 + cg] = (uint16_t)bits;
        }
        __syncthreads();

        if (kt + 1 < 32) {
            pf_l2((const char*)(kb + (size_t)(kt + 1) * TK * DD) + tid * 128);
            pf_l2((const char*)(mk + (size_t)(tid >> 2) * SS + (kt + 1) * TK + (tid & 3) * 16));
        }

        // ---- S = Q K^T: fragments once per ks; split-outer MMA order ----
        float sacc[2][2][4];
#pragma unroll
        for (int mt = 0; mt < 2; ++mt)
#pragma unroll
            for (int nt = 0; nt < 2; ++nt)
#pragma unroll
                for (int e = 0; e < 4; ++e) sacc[mt][nt][e] = 0.0f;

#pragma unroll
        for (int ks = 0; ks < 8; ++ks) {
            uint32_t ah[2][4], al[2][4], bh[4], bl[4];
#pragma unroll
            for (int mt = 0; mt < 2; ++mt) {
                uint32_t ra = (uint32_t)((warpM * 32 + mt * 16) * PITCHB + ks * 32) + a_off;
                ldsm4(ah[mt], sb + OFF_QHI + ra);
                ldsm4(al[mt], sb + OFF_QLO + ra);
            }
            {
                uint32_t rb = (uint32_t)((warpN * 16) * PITCHB + ks * 32) + b_off;
                ldsm4(bh, sb + OFF_KHI + rb);
                ldsm4(bl, sb + OFF_KLO + rb);
            }
#pragma unroll
            for (int mt = 0; mt < 2; ++mt)
#pragma unroll
                for (int nt = 0; nt < 2; ++nt)
                    mma16816(sacc[mt][nt], ah[mt], &bh[nt * 2]);   // hh
#pragma unroll
            for (int mt = 0; mt < 2; ++mt)
#pragma unroll
                for (int nt = 0; nt < 2; ++nt)
                    mma16816(sacc[mt][nt], ah[mt], &bl[nt * 2]);   // hl
#pragma unroll
            for (int mt = 0; mt < 2; ++mt)
#pragma unroll
                for (int nt = 0; nt < 2; ++nt)
                    mma16816(sacc[mt][nt], al[mt], &bh[nt * 2]);   // lh
        }

        // ---- epilogue: ev = exp(s) masked->0; emax & Z ----
#pragma unroll
        for (int mt = 0; mt < 2; ++mt) {
#pragma unroll
            for (int rh = 0; rh < 2; ++rh) {
                const int i = mt * 2 + rh;
                const int row = warpM * 32 + mt * 16 + rh * 8 + g;
                const uint32_t mw = mbits[row * 4 + warpN];
#pragma unroll
                for (int nt = 0; nt < 2; ++nt) {
#pragma unroll
                    for (int e = 0; e < 2; ++e) {
                        float s = sacc[mt][nt][rh * 2 + e] * scale;
                        int bit = nt * 8 + tg * 2 + e;
                        bool um = (mw >> bit) & 1u;
                        float ev = um ? __expf(s) : 0.0f;
                        emax_run[i] = fmaxf(emax_run[i], ev);
                        z_run[i] += ev;
                        sacc[mt][nt][rh * 2 + e] = ev;
                    }
                }
            }
        }

        __syncthreads();   // K smem reads done -> reuse as P
        // ---- mid phase: pack P + V convert (fills the short slot) ----
        {
            char* phi = smem + OFF_KHI;
            char* plo = smem + OFF_KLO;
#pragma unroll
            for (int mt = 0; mt < 2; ++mt)
#pragma unroll
                for (int rh = 0; rh < 2; ++rh) {
                    const int row = warpM * 32 + mt * 16 + rh * 8 + g;
#pragma unroll
                    for (int nt = 0; nt < 2; ++nt) {
                        uint32_t h, l;
                        pack2(sacc[mt][nt][rh * 2], sacc[mt][nt][rh * 2 + 1], h, l);
                        const int col = warpN * 16 + nt * 8 + tg * 2;
                        *(uint32_t*)(phi + row * PITCHP + col * 2) = h;
                        *(uint32_t*)(plo + row * PITCHP + col * 2) = l;
                    }
                }
        }
        cvt_tile(vb + (size_t)kt * TK * DD, smem + OFF_VHI, smem + OFF_VLO, tid);
        if (kt + 1 < 32)
            pf_l2((const char*)(vb + (size_t)(kt + 1) * TK * DD) + tid * 128);
        __syncthreads();

        // ---- e-write to gmem (overlaps PV tensor phase; streaming) ----
#pragma unroll
        for (int mt = 0; mt < 2; ++mt)
#pragma unroll
            for (int rh = 0; rh < 2; ++rh) {
                const int row = warpM * 32 + mt * 16 + rh * 8 + g;
                float* dst = pb + (size_t)row * SP1 + 1 + kt * TK + warpN * 16;
#pragma unroll
                for (int nt = 0; nt < 2; ++nt) {
                    __stcs(dst + nt * 8 + tg * 2,     sacc[mt][nt][rh * 2]);
                    __stcs(dst + nt * 8 + tg * 2 + 1, sacc[mt][nt][rh * 2 + 1]);
                }
            }

        // ---- O += P V: fragments once per ks; split-outer order ----
#pragma unroll
        for (int ks = 0; ks < 4; ++ks) {
            uint32_t ah[2][4], al[2][4], bh[2][4], bl[2][4];
#pragma unroll
            for (int mt = 0; mt < 2; ++mt) {
                uint32_t ra = (uint32_t)((warpM * 32 + mt * 16) * PITCHP + ks * 32) + a_offP;
                ldsm4(ah[mt], sb + OFF_KHI + ra);
                ldsm4(al[mt], sb + OFF_KLO + ra);
            }
#pragma unroll
            for (int n2 = 0; n2 < 2; ++n2) {
                uint32_t rb = (uint32_t)((ks * 16) * PITCHB + (warpN * 32 + n2 * 16) * 2) + a_off;
                ldsm4t(bh[n2], sb + OFF_VHI + rb);
                ldsm4t(bl[n2], sb + OFF_VLO + rb);
            }
#pragma unroll
            for (int mt = 0; mt < 2; ++mt)
#pragma unroll
                for (int nt = 0; nt < 4; ++nt)
                    mma16816(oacc[mt][nt], ah[mt], &bh[nt >> 1][(nt & 1) * 2]);  // hh
#pragma unroll
            for (int mt = 0; mt < 2; ++mt)
#pragma unroll
                for (int nt = 0; nt < 4; ++nt)
                    mma16816(oacc[mt][nt], ah[mt], &bl[nt >> 1][(nt & 1) * 2]);  // hl
#pragma unroll
            for (int mt = 0; mt < 2; ++mt)
#pragma unroll
                for (int nt = 0; nt < 4; ++nt)
                    mma16816(oacc[mt][nt], al[mt], &bh[nt >> 1][(nt & 1) * 2]);  // lh
        }
    }

    // ---- reduce emax (max) and Z (sum) ----
#pragma unroll
    for (int off = 1; off <= 2; off <<= 1) {
#pragma unroll
        for (int i = 0; i < 4; ++i) {
            emax_run[i] = fmaxf(emax_run[i], __shfl_xor_sync(0xffffffffu, emax_run[i], off));
            z_run[i] += __shfl_xor_sync(0xffffffffu, z_run[i], off);
        }
    }
    __syncthreads();
    if (tg == 0) {
#pragma unroll
        for (int i = 0; i < 4; ++i) {
            int row = warpM * 32 + (i >> 1) * 16 + (i & 1) * 8 + g;
            redM[warpN * 64 + row] = emax_run[i];
            redZ[warpN * 64 + row] = z_run[i];
        }
    }
    __syncthreads();
    if (tid < 64) {
        float em = redM[tid], z = redZ[tid];
#pragma unroll
        for (int w = 1; w < 4; ++w) {
            em = fmaxf(em, redM[w * 64 + tid]);
            z += redZ[w * 64 + tid];
        }
        float inv = 1.0f / (em + z);       // denom = e^m + sum e^s
        sInv[tid] = inv;
        pb[(size_t)tid * SP1] = 0.0f;      // sink: exp(-1e9 - m) == 0 in fp32
    }
    __syncthreads();

    // ---- write O (scaled) ----
#pragma unroll
    for (int mt = 0; mt < 2; ++mt)
#pragma unroll
        for (int rh = 0; rh < 2; ++rh) {
            int row = warpM * 32 + mt * 16 + rh * 8 + g;
            float inv = sInv[row];
#pragma unroll
            for (int nt = 0; nt < 4; ++nt) {
                int col = warpN * 32 + nt * 8 + tg * 2;
                float2 val = make_float2(oacc[mt][nt][rh * 2] * inv,
                                         oacc[mt][nt][rh * 2 + 1] * inv);
                *(float2*)(ob + (size_t)row * DD + col) = val;
            }
        }

    // ---- rescale p: float4 body with alignment peel ----
    {
#pragma unroll 1
        for (int rr = 0; rr < 8; ++rr) {
            const int row = wid * 8 + rr;
            const float inv = sInv[row];
            float* ga = pb + (size_t)row * SP1 + 1;
            const int head = (4 - ((row * SP1 + 1) & 3)) & 3;
            if (lane < head) ga[lane] *= inv;
            const int body4 = (SS - head) >> 2;
            float4* g4 = (float4*)(ga + head);
#pragma unroll 4
            for (int c = lane; c < body4; c += 32) {
                float4 x = __ldcs(g4 + c);
                x.x *= inv; x.y *= inv; x.z *= inv; x.w *= inv;
                __stcs(g4 + c, x);
            }
            const int done = head + body4 * 4;
            if (lane < (SS - done)) ga[done + lane] *= inv;
        }
    }
}

extern "C" void kernel_launch(void* const* d_in, const int* in_sizes, int n_in,
                              void* d_out, int out_size)
{
    const float* q    = (const float*)d_in[0];
    const float* k    = (const float*)d_in[1];
    const float* v    = (const float*)d_in[2];
    const int*   mask = (const int*)d_in[3];

    const long OUT_N = (long)BB * SS * DD;
    const long P_N   = (long)BB * SS * SP1;

    float* out = (float*)d_out;
    float* p   = ((long)out_size == P_N) ? out : out + OUT_N;

    cudaFuncSetAttribute(qa_sp6_kernel,
                         cudaFuncAttributeMaxDynamicSharedMemorySize, SMEM_TOTAL);
    dim3 grid(SS / TQ, BB);
    qa_sp6_kernel<<<grid, NTH, SMEM_TOTAL>>>(q, k, v, mask, out, p);
}